// round 15
// baseline (speedup 1.0000x reference)
#include <cuda_runtime.h>
#include <cuda_fp16.h>
#include <cstdint>
#include <cstddef>

// ---------------- problem constants ----------------
constexpr int Bn  = 6;
constexpr int Nn  = 4096;
constexpr int QD  = 320;
constexpr int CN  = 77;
constexpr int CD  = 768;
constexpr int Hh  = 8;
constexpr int DH  = 40;
constexpr int ID  = Hh * DH;          // 320 inner dim
constexpr float SCALE = 0.15811388300841897f; // 40^-0.5

constexpr int MROWS = Bn * Nn;        // 24576
constexpr int KVROWS = Bn * CN;       // 462

// single extern shared symbol (attn only)
extern __shared__ char smem_raw[];

// ---------------- scratch (static device memory; no allocs allowed) ------
__device__ float  g_q [ (size_t)MROWS * ID ];     // q projection, (B*N, 320) fp32
__device__ __half g_oh[ (size_t)MROWS * ID ];     // attn@v merged heads, fp16
__device__ __half g_xh[ (size_t)MROWS * ID ];     // x converted to fp16
__device__ float  g_kv[ (size_t)KVROWS * 2 * ID ];// (B*CN, 640): [0,320)=K, [320,640)=V
__device__ __half g_wt[ 2 * 320 * 320 ];          // Wq^T, Wo^T (fp16, N-major)

// ---------------- helpers ----------------
__device__ __forceinline__ uint32_t smem_u32(const void* p) {
    uint32_t a;
    asm("{ .reg .u64 t; cvta.to.shared.u64 t, %1; cvt.u32.u64 %0, t; }" : "=r"(a) : "l"(p));
    return a;
}
__device__ __forceinline__ uint32_t f2tf32(float f) {
    uint32_t r;
    asm("cvt.rna.tf32.f32 %0, %1;" : "=r"(r) : "f"(f));
    return r;
}
__device__ __forceinline__ uint4 tf32x4(float4 v) {
    uint4 r;
    r.x = f2tf32(v.x); r.y = f2tf32(v.y);
    r.z = f2tf32(v.z); r.w = f2tf32(v.w);
    return r;
}
// FFMA-only exp (relative error ~2.5e-6)
__device__ __forceinline__ float fast_exp(float x) {
    x = fmaxf(x, -60.f);
    float y = x * 1.4426950408889634f;
    int   n = __float2int_rn(y);
    float f = y - (float)n;
    float t = f * 0.6931471805599453f;
    float p = 8.3333333333e-3f;
    p = fmaf(p, t, 4.1666666667e-2f);
    p = fmaf(p, t, 1.6666666667e-1f);
    p = fmaf(p, t, 0.5f);
    p = fmaf(p, t, 1.0f);
    p = fmaf(p, t, 1.0f);
    return __int_as_float(__float_as_int(p) + (n << 23));
}

#define MMA_TF32(acc, a0, a1, a2, a3, b0, b1)                                   \
    asm volatile(                                                               \
        "mma.sync.aligned.m16n8k8.row.col.f32.tf32.tf32.f32 "                   \
        "{%0,%1,%2,%3}, {%4,%5,%6,%7}, {%8,%9}, {%0,%1,%2,%3};\n"               \
        : "+f"(acc[0]), "+f"(acc[1]), "+f"(acc[2]), "+f"(acc[3])                \
        : "r"(a0), "r"(a1), "r"(a2), "r"(a3), "r"(b0), "r"(b1))

#define MMA_F16(acc, a0, a1, a2, a3, b0, b1)                                    \
    asm volatile(                                                               \
        "mma.sync.aligned.m16n8k16.row.col.f32.f16.f16.f32 "                    \
        "{%0,%1,%2,%3}, {%4,%5,%6,%7}, {%8,%9}, {%0,%1,%2,%3};\n"               \
        : "+f"(acc[0]), "+f"(acc[1]), "+f"(acc[2]), "+f"(acc[3])                \
        : "r"(a0), "r"(a1), "r"(a2), "r"(a3), "r"(b0), "r"(b1))

#define LDMATRIX_X4(r0, r1, r2, r3, addr)                                       \
    asm volatile("ldmatrix.sync.aligned.m8n8.x4.shared.b16 {%0,%1,%2,%3}, [%4];"\
        : "=r"(r0), "=r"(r1), "=r"(r2), "=r"(r3) : "r"(addr))

#define CP_ASYNC16(saddr, gptr)                                                 \
    asm volatile("cp.async.ca.shared.global [%0], [%1], 16;"                    \
        :: "r"(saddr), "l"(gptr) : "memory")
#define CP_COMMIT()  asm volatile("cp.async.commit_group;" ::: "memory")
#define CP_WAIT0()   asm volatile("cp.async.wait_group 0;" ::: "memory")

// =====================================================================
// x -> fp16 convert (one shot): g_xh = half(x)
// =====================================================================
__global__ void convert_x(const float* __restrict__ x)
{
    const size_t i = ((size_t)blockIdx.x * blockDim.x + threadIdx.x) * 4;
    float4 v = *(const float4*)(x + i);
    __half2 h0 = __floats2half2_rn(v.x, v.y);
    __half2 h1 = __floats2half2_rn(v.z, v.w);
    uint2 u;
    u.x = *(const uint32_t*)&h0;
    u.y = *(const uint32_t*)&h1;
    *(uint2*)(g_xh + i) = u;
}

// =====================================================================
// W transpose + fp16 convert: g_wt[sel][n][k] = half(W[k][n]), 320x320
// =====================================================================
__global__ void transpose_w(const float* __restrict__ Wq, const float* __restrict__ Wo)
{
    __shared__ float tile[32][33];
    const float* W = (blockIdx.z == 0) ? Wq : Wo;
    __half* Wt = g_wt + (size_t)blockIdx.z * 320 * 320;
    const int kBase = blockIdx.y * 32;
    const int nBase = blockIdx.x * 32;
    const int tx = threadIdx.x, ty = threadIdx.y;  // (32, 8)
    #pragma unroll
    for (int i = 0; i < 4; i++)
        tile[ty + 8 * i][tx] = W[(size_t)(kBase + ty + 8 * i) * 320 + nBase + tx];
    __syncthreads();
    #pragma unroll
    for (int i = 0; i < 4; i++)
        Wt[(size_t)(nBase + ty + 8 * i) * 320 + kBase + tx] =
            __float2half_rn(tile[tx][ty + 8 * i]);
}

// =====================================================================
// FP16 tensor-core GEMM v5: C(24576x320) = A(fp16) @ W (+bias), fp32 acc.
// BM=128, BN=64, BK=32, 256 threads (8 warps, 4M x 2N, warp 32x32).
// cp.async double-buffered staging; ldmatrix.x4; stride 40 conflict-free.
// =====================================================================
template<bool BIAS>
__global__ void __launch_bounds__(256) gemm_h16(
    const __half* __restrict__ A,      // (24576, 320) fp16
    const __half* __restrict__ Wt,     // (320, 320) N-major fp16
    const float*  __restrict__ bias,   // (320) or null
    float* __restrict__ C)             // (24576, 320)
{
    constexpr int Nc = 320, K = 320;
    constexpr int HS = 40;
    constexpr int NSTAGE = K / 32;     // 10

    __shared__ __half Ah[2][128][HS];  // 2 x 10,240 B
    __shared__ __half Bh[2][64][HS];   // 2 x  5,120 B

    const int tid  = threadIdx.x;
    const int lane = tid & 31;
    const int wid  = tid >> 5;
    const int warpM = wid & 3;         // 32-row slice
    const int warpN = wid >> 2;        // 32-col slice
    const int g = lane >> 2;
    const int t = lane & 3;
    const int lrow = lane & 7;
    const int lgrp = lane >> 3;

    const int rowBase = blockIdx.y * 128;
    const int colBase = blockIdx.x * 64;

    // cp.async staging maps
    const int arow = tid >> 1;           // 0..127
    const int acol = (tid & 1) * 16;     // halves 0 or 16 (2x16B chunks)
    const int brow = tid >> 2;           // 0..63
    const int bcol = (tid & 3) * 8;      // halves {0,8,16,24} (1x16B chunk)

    const __half* aPtr = A  + (size_t)(rowBase + arow) * K + acol;
    const __half* bPtr = Wt + (size_t)(colBase + brow) * K + bcol;

    float acc[2][4][4];
    #pragma unroll
    for (int mt = 0; mt < 2; mt++)
        #pragma unroll
        for (int nt = 0; nt < 4; nt++)
            #pragma unroll
            for (int r = 0; r < 4; r++) acc[mt][nt][r] = 0.f;

    const int a_row = (lgrp & 1) * 8 + lrow;
    const int a_col = (lgrp >> 1) * 8;
    const int b_row = (lgrp >> 1) * 8 + lrow;
    const int b_col = (lgrp & 1) * 8;

    // prefetch stage 0
    {
        CP_ASYNC16(smem_u32(&Ah[0][arow][acol]),     aPtr);
        CP_ASYNC16(smem_u32(&Ah[0][arow][acol + 8]), aPtr + 8);
        CP_ASYNC16(smem_u32(&Bh[0][brow][bcol]),     bPtr);
        CP_COMMIT();
    }

    for (int s = 0; s < NSTAGE; s++) {
        const int buf = s & 1;
        CP_WAIT0();
        __syncthreads();

        if (s + 1 < NSTAGE) {
            const int k0 = (s + 1) * 32;
            CP_ASYNC16(smem_u32(&Ah[buf ^ 1][arow][acol]),     aPtr + k0);
            CP_ASYNC16(smem_u32(&Ah[buf ^ 1][arow][acol + 8]), aPtr + k0 + 8);
            CP_ASYNC16(smem_u32(&Bh[buf ^ 1][brow][bcol]),     bPtr + k0);
            CP_COMMIT();
        }

        #pragma unroll
        for (int kk = 0; kk < 2; kk++) {
            const int kc = kk * 16;
            uint32_t afr[2][4], bfr[4][2];
            #pragma unroll
            for (int mt = 0; mt < 2; mt++) {
                uint32_t addr = smem_u32(&Ah[buf][warpM * 32 + mt * 16 + a_row][kc + a_col]);
                LDMATRIX_X4(afr[mt][0], afr[mt][1], afr[mt][2], afr[mt][3], addr);
            }
            #pragma unroll
            for (int nb = 0; nb < 2; nb++) {
                uint32_t addr = smem_u32(&Bh[buf][warpN * 32 + nb * 16 + b_row][kc + b_col]);
                LDMATRIX_X4(bfr[2 * nb][0], bfr[2 * nb][1],
                            bfr[2 * nb + 1][0], bfr[2 * nb + 1][1], addr);
            }
            #pragma unroll
            for (int mt = 0; mt < 2; mt++)
                #pragma unroll
                for (int nt = 0; nt < 4; nt++)
                    MMA_F16(acc[mt][nt], afr[mt][0], afr[mt][1], afr[mt][2], afr[mt][3],
                            bfr[nt][0], bfr[nt][1]);
        }
        __syncthreads();
    }

    // epilogue
    #pragma unroll
    for (int mt = 0; mt < 2; mt++) {
        const int row = rowBase + warpM * 32 + mt * 16 + g;
        #pragma unroll
        for (int nt = 0; nt < 4; nt++) {
            const int col = colBase + warpN * 32 + nt * 8 + 2 * t;
            float b0 = 0.f, b1 = 0.f;
            if (BIAS) { b0 = bias[col]; b1 = bias[col + 1]; }
            float2 lo, hi;
            lo.x = acc[mt][nt][0] + b0; lo.y = acc[mt][nt][1] + b1;
            hi.x = acc[mt][nt][2] + b0; hi.y = acc[mt][nt][3] + b1;
            *(float2*)&C[(size_t)row * Nc + col]       = lo;
            *(float2*)&C[(size_t)(row + 8) * Nc + col] = hi;
        }
    }
}

// =====================================================================
// K/V projection in ONE launch (fp32 FFMA; tiny: 462x640x768)
// =====================================================================
__global__ void __launch_bounds__(256) sgemm_kv(
    const float* __restrict__ A,
    const float* __restrict__ Wk,
    const float* __restrict__ Wv)
{
    constexpr int M = KVROWS, K = CD, NW = ID, NC = 2 * ID;
    __shared__ float As[16][64 + 4];
    __shared__ float Bs[16][64];

    const int tid = threadIdx.x;
    const int colBase = blockIdx.x * 64;
    const int rowBase = blockIdx.y * 64;
    const float* Bm = (colBase < NW) ? Wk : Wv;
    const int cb = (colBase < NW) ? colBase : colBase - NW;

    const int tx = tid & 15, ty = tid >> 4;
    const int ar = tid >> 2;
    const int ac = (tid & 3) << 2;
    const int br = tid >> 4;
    const int bc = (tid & 15) << 2;

    float acc[4][4];
    #pragma unroll
    for (int i = 0; i < 4; i++)
        #pragma unroll
        for (int j = 0; j < 4; j++) acc[i][j] = 0.f;

    for (int k0 = 0; k0 < K; k0 += 16) {
        const int grow = rowBase + ar;
        float4 a = (grow < M) ? *(const float4*)&A[(size_t)grow * K + k0 + ac]
                              : make_float4(0.f, 0.f, 0.f, 0.f);
        float4 b = *(const float4*)&Bm[(size_t)(k0 + br) * NW + cb + bc];
        As[ac+0][ar] = a.x; As[ac+1][ar] = a.y; As[ac+2][ar] = a.z; As[ac+3][ar] = a.w;
        *(float4*)&Bs[br][bc] = b;
        __syncthreads();

        #pragma unroll
        for (int kk = 0; kk < 16; kk++) {
            float av[4], bv[4];
            #pragma unroll
            for (int i = 0; i < 4; i++) av[i] = As[kk][ty * 4 + i];
            #pragma unroll
            for (int j = 0; j < 4; j++) bv[j] = Bs[kk][tx * 4 + j];
            #pragma unroll
            for (int i = 0; i < 4; i++)
                #pragma unroll
                for (int j = 0; j < 4; j++) acc[i][j] += av[i] * bv[j];
        }
        __syncthreads();
    }

    #pragma unroll
    for (int i = 0; i < 4; i++) {
        const int r = rowBase + ty * 4 + i;
        if (r < M) {
            float4 v; v.x = acc[i][0]; v.y = acc[i][1]; v.z = acc[i][2]; v.w = acc[i][3];
            *(float4*)&g_kv[(size_t)r * NC + colBase + tx * 4] = v;
        }
    }
}

// =====================================================================
// Attention v6 (R14): register softmax + shuffle PV fragments,
// K/V stride 44, fp16 output to g_oh.
// =====================================================================
constexpr int KVS = 44;
constexpr int ATTN_SMEM_B = (80 * KVS * 2) * 4;       // 28,160 B

__global__ void __launch_bounds__(256) attn_kernel(
    const float* __restrict__ q,    // (B*N, 320)
    float* __restrict__ sim)        // (B,H,N,77)
{
    float* Ks = (float*)smem_raw;              // [80][44]
    float* Vs = Ks + 80 * KVS;                 // [80][44]

    const int bh = blockIdx.y;
    const int b = bh >> 3;
    const int h = bh & 7;
    const int tid  = threadIdx.x;
    const int lane = tid & 31;
    const int wid  = tid >> 5;
    const int g = lane >> 2;
    const int t = lane & 3;
    const int nBase = blockIdx.x * 128;
    const int m0 = wid * 16;

    float qf[5][4];
    {
        const float* qb = q + (size_t)(b * Nn + nBase + m0 + g) * ID + h * DH;
        #pragma unroll
        for (int ks = 0; ks < 5; ks++) {
            const int kc = ks * 8;
            qf[ks][0] = qb[kc + t];
            qf[ks][1] = qb[8 * ID + kc + t];
            qf[ks][2] = qb[kc + t + 4];
            qf[ks][3] = qb[8 * ID + kc + t + 4];
        }
    }

    for (int idx = tid; idx < CN * 10; idx += 256) {
        const int r = idx / 10, c4 = (idx - r * 10) * 4;
        const float* base = g_kv + (size_t)(b * CN + r) * (2 * ID) + h * DH + c4;
        *(uint4*)&Ks[r * KVS + c4] = tf32x4(*(const float4*)(base));
        *(uint4*)&Vs[r * KVS + c4] = tf32x4(*(const float4*)(base + ID));
    }
    if (tid < 120) {
        const int r = CN + tid / DH;
        const int c = tid % DH;
        Ks[r * KVS + c] = 0.f;
        Vs[r * KVS + c] = 0.f;
    }
    __syncthreads();

    float acc[10][4];
    #pragma unroll
    for (int nt = 0; nt < 10; nt++)
        #pragma unroll
        for (int r = 0; r < 4; r++) acc[nt][r] = 0.f;

    #pragma unroll
    for (int ks = 0; ks < 5; ks++) {
        const int kc = ks * 8;
        const uint32_t a0 = f2tf32(qf[ks][0]);
        const uint32_t a1 = f2tf32(qf[ks][1]);
        const uint32_t a2 = f2tf32(qf[ks][2]);
        const uint32_t a3 = f2tf32(qf[ks][3]);
        #pragma unroll
        for (int nt = 0; nt < 10; nt++) {
            const int n0 = nt * 8 + g;
            uint32_t b0 = __float_as_uint(Ks[n0 * KVS + kc + t    ]);
            uint32_t b1 = __float_as_uint(Ks[n0 * KVS + kc + t + 4]);
            MMA_TF32(acc[nt], a0, a1, a2, a3, b0, b1);
        }
    }
    #pragma unroll
    for (int nt = 0; nt < 10; nt++)
        #pragma unroll
        for (int r = 0; r < 4; r++) acc[nt][r] *= SCALE;

    {
        float* s0 = sim + ((size_t)bh * Nn + nBase + m0 + g) * CN;
        float* s1 = s0 + 8 * (size_t)CN;
        #pragma unroll
        for (int nt = 0; nt < 10; nt++) {
            const int c = nt * 8 + 2 * t;
            if (c < CN) {
                s0[c] = acc[nt][0];
                s1[c] = acc[nt][2];
            }
            if (c + 1 < CN) {
                s0[c + 1] = acc[nt][1];
                s1[c + 1] = acc[nt][3];
            }
        }
    }

    {
        const bool in0 = (t <= 2);
        const bool in1 = (t <= 1);
        float mx0 = -1e30f, mx1 = -1e30f;
        #pragma unroll
        for (int nt = 0; nt < 9; nt++) {
            mx0 = fmaxf(mx0, fmaxf(acc[nt][0], acc[nt][1]));
            mx1 = fmaxf(mx1, fmaxf(acc[nt][2], acc[nt][3]));
        }
        if (in0) { mx0 = fmaxf(mx0, acc[9][0]); mx1 = fmaxf(mx1, acc[9][2]); }
        if (in1) { mx0 = fmaxf(mx0, acc[9][1]); mx1 = fmaxf(mx1, acc[9][3]); }
        mx0 = fmaxf(mx0, __shfl_xor_sync(0xFFFFFFFF, mx0, 1));
        mx0 = fmaxf(mx0, __shfl_xor_sync(0xFFFFFFFF, mx0, 2));
        mx1 = fmaxf(mx1, __shfl_xor_sync(0xFFFFFFFF, mx1, 1));
        mx1 = fmaxf(mx1, __shfl_xor_sync(0xFFFFFFFF, mx1, 2));

        float s0 = 0.f, s1 = 0.f;
        #pragma unroll
        for (int nt = 0; nt < 10; nt++) {
            float e0 = fast_exp(acc[nt][0] - mx0);
            float e1 = fast_exp(acc[nt][1] - mx0);
            float e2 = fast_exp(acc[nt][2] - mx1);
            float e3 = fast_exp(acc[nt][3] - mx1);
            if (nt == 9) {
                if (!in0) { e0 = 0.f; e2 = 0.f; }
                if (!in1) { e1 = 0.f; e3 = 0.f; }
            }
            acc[nt][0] = e0; acc[nt][1] = e1;
            acc[nt][2] = e2; acc[nt][3] = e3;
            s0 += e0 + e1;
            s1 += e2 + e3;
        }
        s0 += __shfl_xor_sync(0xFFFFFFFF, s0, 1);
        s0 += __shfl_xor_sync(0xFFFFFFFF, s0, 2);
        s1 += __shfl_xor_sync(0xFFFFFFFF, s1, 1);
        s1 += __shfl_xor_sync(0xFFFFFFFF, s1, 2);
        const float inv0 = 1.f / s0;
        const float inv1 = 1.f / s1;

        float w = 1.f;
        if (b == 3) w = -2.f; else if (b == 5) w = 5.f;
        if (t == 1) { acc[0][0] *= w; acc[0][2] *= w; }

        #pragma unroll
        for (int nt = 0; nt < 10; nt++) {
            acc[nt][0] = __uint_as_float(f2tf32(acc[nt][0] * inv0));
            acc[nt][1] = __uint_as_float(f2tf32(acc[nt][1] * inv0));
            acc[nt][2] = __uint_as_float(f2tf32(acc[nt][2] * inv1));
            acc[nt][3] = __uint_as_float(f2tf32(acc[nt][3] * inv1));
        }
    }

    {
        const int base = lane & ~3;
        const int srcA = base | (t >> 1);
        const int srcB = base | (2 + (t >> 1));
        const bool odd = (t & 1);

        float oacc[5][4];
        #pragma unroll
        for (int nt = 0; nt < 5; nt++)
            #pragma unroll
            for (int r = 0; r < 4; r++) oacc[nt][r] = 0.f;

        #pragma unroll
        for (int ks = 0; ks < 10; ks++) {
            const int kc = ks * 8;
            float xA0 = __shfl_sync(0xFFFFFFFF, acc[ks][0], srcA);
            float yA0 = __shfl_sync(0xFFFFFFFF, acc[ks][1], srcA);
            float xA1 = __shfl_sync(0xFFFFFFFF, acc[ks][2], srcA);
            float yA1 = __shfl_sync(0xFFFFFFFF, acc[ks][3], srcA);
            float xB0 = __shfl_sync(0xFFFFFFFF, acc[ks][0], srcB);
            float yB0 = __shfl_sync(0xFFFFFFFF, acc[ks][1], srcB);
            float xB1 = __shfl_sync(0xFFFFFFFF, acc[ks][2], srcB);
            float yB1 = __shfl_sync(0xFFFFFFFF, acc[ks][3], srcB);

            uint32_t a0 = __float_as_uint(odd ? yA0 : xA0);
            uint32_t a1 = __float_as_uint(odd ? yA1 : xA1);
            uint32_t a2 = __float_as_uint(odd ? yB0 : xB0);
            uint32_t a3 = __float_as_uint(odd ? yB1 : xB1);

            #pragma unroll
            for (int nt = 0; nt < 5; nt++) {
                const int n0 = nt * 8 + g;
                uint32_t b0 = __float_as_uint(Vs[(kc + t    ) * KVS + n0]);
                uint32_t b1 = __float_as_uint(Vs[(kc + t + 4) * KVS + n0]);
                MMA_TF32(oacc[nt], a0, a1, a2, a3, b0, b1);
            }
        }

        __half* o0 = g_oh + ((size_t)(b * Nn + nBase + m0 + g    )) * ID + h * DH;
        __half* o1 = g_oh + ((size_t)(b * Nn + nBase + m0 + g + 8)) * ID + h * DH;
        #pragma unroll
        for (int nt = 0; nt < 5; nt++) {
            const int c = nt * 8 + 2 * t;
            __half2 lo = __floats2half2_rn(oacc[nt][0], oacc[nt][1]);
            __half2 hi = __floats2half2_rn(oacc[nt][2], oacc[nt][3]);
            *(__half2*)(o0 + c) = lo;
            *(__half2*)(o1 + c) = hi;
        }
    }
}

// =====================================================================
// launch
// =====================================================================
extern "C" void kernel_launch(void* const* d_in, const int* in_sizes, int n_in,
                              void* d_out, int out_size)
{
    const float* x   = (const float*)d_in[0];
    const float* ctx = (const float*)d_in[1];
    const float* Wq  = (const float*)d_in[2];
    const float* Wk  = (const float*)d_in[3];
    const float* Wv  = (const float*)d_in[4];
    const float* Wo  = (const float*)d_in[5];
    const float* bo  = (const float*)d_in[6];
    // d_in[7] = time (unused: reweight always applies for time >= 0)

    float* out = (float*)d_out;                       // (B, N, 320)
    float* sim = out + (size_t)Bn * Nn * QD;          // (B, H, N, 77)

    float* qp = nullptr;
    __half *wt = nullptr, *xh = nullptr, *oh = nullptr;
    cudaGetSymbolAddress((void**)&qp, g_q);
    cudaGetSymbolAddress((void**)&wt, g_wt);
    cudaGetSymbolAddress((void**)&xh, g_xh);
    cudaGetSymbolAddress((void**)&oh, g_oh);

    cudaFuncSetAttribute(attn_kernel, cudaFuncAttributeMaxDynamicSharedMemorySize,
                         ATTN_SMEM_B);

    // x -> fp16 (7.86M elems, 4/thread)
    convert_x<<<(MROWS * ID) / (256 * 4), 256>>>(x);

    // transpose + fp16 convert Wq, Wo
    transpose_w<<<dim3(10, 10, 2), dim3(32, 8)>>>(Wq, Wo);

    // K & V projections (one launch)
    sgemm_kv<<<dim3((2 * ID) / 64, (KVROWS + 63) / 64), 256>>>(ctx, Wk, Wv);

    // Q projection (fp16 A + fp16 W, cp.async double-buffered)
    gemm_h16<false><<<dim3(320 / 64, MROWS / 128), 256>>>(xh, wt, nullptr, qp);

    // fused attention (register softmax, fp16 out)
    attn_kernel<<<dim3(Nn / 128, Bn * Hh), 256, ATTN_SMEM_B>>>(qp, sim);

    // output projection + bias (fp16 A from attn, cp.async double-buffered)
    gemm_h16<true><<<dim3(320 / 64, MROWS / 128), 256>>>(oh, wt + 320 * 320, bo, out);
}

// round 16
// speedup vs baseline: 1.0267x; 1.0267x over previous
#include <cuda_runtime.h>
#include <cuda_fp16.h>
#include <cstdint>
#include <cstddef>

// ---------------- problem constants ----------------
constexpr int Bn  = 6;
constexpr int Nn  = 4096;
constexpr int QD  = 320;
constexpr int CN  = 77;
constexpr int CD  = 768;
constexpr int Hh  = 8;
constexpr int DH  = 40;
constexpr int ID  = Hh * DH;          // 320 inner dim
constexpr float SCALE = 0.15811388300841897f; // 40^-0.5

constexpr int MROWS = Bn * Nn;        // 24576
constexpr int KVROWS = Bn * CN;       // 462

// single extern shared symbol (attn only)
extern __shared__ char smem_raw[];

// ---------------- scratch (static device memory; no allocs allowed) ------
__device__ __half g_qh[ (size_t)MROWS * ID ];     // q projection, fp16
__device__ __half g_oh[ (size_t)MROWS * ID ];     // attn@v merged heads, fp16
__device__ __half g_xh[ (size_t)MROWS * ID ];     // x converted to fp16
__device__ float  g_kv[ (size_t)KVROWS * 2 * ID ];// (B*CN, 640): [0,320)=K, [320,640)=V
__device__ __half g_wt[ 2 * 320 * 320 ];          // Wq^T, Wo^T (fp16, N-major)

// ---------------- helpers ----------------
__device__ __forceinline__ uint32_t smem_u32(const void* p) {
    uint32_t a;
    asm("{ .reg .u64 t; cvta.to.shared.u64 t, %1; cvt.u32.u64 %0, t; }" : "=r"(a) : "l"(p));
    return a;
}
__device__ __forceinline__ uint32_t f2tf32(float f) {
    uint32_t r;
    asm("cvt.rna.tf32.f32 %0, %1;" : "=r"(r) : "f"(f));
    return r;
}
__device__ __forceinline__ uint4 tf32x4(float4 v) {
    uint4 r;
    r.x = f2tf32(v.x); r.y = f2tf32(v.y);
    r.z = f2tf32(v.z); r.w = f2tf32(v.w);
    return r;
}
// FFMA-only exp (relative error ~2.5e-6)
__device__ __forceinline__ float fast_exp(float x) {
    x = fmaxf(x, -60.f);
    float y = x * 1.4426950408889634f;
    int   n = __float2int_rn(y);
    float f = y - (float)n;
    float t = f * 0.6931471805599453f;
    float p = 8.3333333333e-3f;
    p = fmaf(p, t, 4.1666666667e-2f);
    p = fmaf(p, t, 1.6666666667e-1f);
    p = fmaf(p, t, 0.5f);
    p = fmaf(p, t, 1.0f);
    p = fmaf(p, t, 1.0f);
    return __int_as_float(__float_as_int(p) + (n << 23));
}

#define MMA_TF32(acc, a0, a1, a2, a3, b0, b1)                                   \
    asm volatile(                                                               \
        "mma.sync.aligned.m16n8k8.row.col.f32.tf32.tf32.f32 "                   \
        "{%0,%1,%2,%3}, {%4,%5,%6,%7}, {%8,%9}, {%0,%1,%2,%3};\n"               \
        : "+f"(acc[0]), "+f"(acc[1]), "+f"(acc[2]), "+f"(acc[3])                \
        : "r"(a0), "r"(a1), "r"(a2), "r"(a3), "r"(b0), "r"(b1))

#define MMA_F16(acc, a0, a1, a2, a3, b0, b1)                                    \
    asm volatile(                                                               \
        "mma.sync.aligned.m16n8k16.row.col.f32.f16.f16.f32 "                    \
        "{%0,%1,%2,%3}, {%4,%5,%6,%7}, {%8,%9}, {%0,%1,%2,%3};\n"               \
        : "+f"(acc[0]), "+f"(acc[1]), "+f"(acc[2]), "+f"(acc[3])                \
        : "r"(a0), "r"(a1), "r"(a2), "r"(a3), "r"(b0), "r"(b1))

#define LDMATRIX_X4(r0, r1, r2, r3, addr)                                       \
    asm volatile("ldmatrix.sync.aligned.m8n8.x4.shared.b16 {%0,%1,%2,%3}, [%4];"\
        : "=r"(r0), "=r"(r1), "=r"(r2), "=r"(r3) : "r"(addr))

// =====================================================================
// x -> fp16 convert (one shot): g_xh = half(x)
// =====================================================================
__global__ void convert_x(const float* __restrict__ x)
{
    const size_t i = ((size_t)blockIdx.x * blockDim.x + threadIdx.x) * 4;
    float4 v = *(const float4*)(x + i);
    __half2 h0 = __floats2half2_rn(v.x, v.y);
    __half2 h1 = __floats2half2_rn(v.z, v.w);
    uint2 u;
    u.x = *(const uint32_t*)&h0;
    u.y = *(const uint32_t*)&h1;
    *(uint2*)(g_xh + i) = u;
}

// =====================================================================
// W transpose + fp16 convert: g_wt[sel][n][k] = half(W[k][n]), 320x320
// =====================================================================
__global__ void transpose_w(const float* __restrict__ Wq, const float* __restrict__ Wo)
{
    __shared__ float tile[32][33];
    const float* W = (blockIdx.z == 0) ? Wq : Wo;
    __half* Wt = g_wt + (size_t)blockIdx.z * 320 * 320;
    const int kBase = blockIdx.y * 32;
    const int nBase = blockIdx.x * 32;
    const int tx = threadIdx.x, ty = threadIdx.y;  // (32, 8)
    #pragma unroll
    for (int i = 0; i < 4; i++)
        tile[ty + 8 * i][tx] = W[(size_t)(kBase + ty + 8 * i) * 320 + nBase + tx];
    __syncthreads();
    #pragma unroll
    for (int i = 0; i < 4; i++)
        Wt[(size_t)(nBase + ty + 8 * i) * 320 + kBase + tx] =
            __float2half_rn(tile[tx][ty + 8 * i]);
}

// =====================================================================
// FP16 tensor-core GEMM (R14-proven, 33.3us): BM=128, BN=64, BK=32,
// 128 threads (4 warps 2Mx2N, warp 64x32), ldmatrix.x4, stride-40 smem.
// HALF_OUT: epilogue writes __half (for q); else fp32 (+bias) to out.
// =====================================================================
template<bool BIAS, bool HALF_OUT>
__global__ void __launch_bounds__(128) gemm_h16(
    const __half* __restrict__ A,      // (24576, 320) fp16
    const __half* __restrict__ Wt,     // (320, 320) N-major fp16
    const float*  __restrict__ bias,   // (320) or null
    float* __restrict__ C,             // fp32 out (when !HALF_OUT)
    __half* __restrict__ Ch)           // fp16 out (when HALF_OUT)
{
    constexpr int Nc = 320, K = 320;
    constexpr int BK = 32;
    constexpr int HS = 40;

    __shared__ __half Ah[128][HS];
    __shared__ __half Bh[64][HS];

    const int tid  = threadIdx.x;
    const int lane = tid & 31;
    const int wid  = tid >> 5;
    const int warpM = wid & 1;
    const int warpN = wid >> 1;
    const int g = lane >> 2;
    const int t = lane & 3;
    const int lrow = lane & 7;
    const int lgrp = lane >> 3;

    const int rowBase = blockIdx.y * 128;
    const int colBase = blockIdx.x * 64;

    const int sr = tid >> 2;          // 0..31
    const int sc = (tid & 3) * 8;     // half col {0,8,16,24}

    const __half* aPtr = A  + (size_t)(rowBase + sr) * K + sc;
    const __half* bPtr = Wt + (size_t)(colBase + sr) * K + sc;

    uint4 aR[4], bR[2];
    #pragma unroll
    for (int i = 0; i < 4; i++) aR[i] = *(const uint4*)(aPtr + (size_t)(32 * i) * K);
    bR[0] = *(const uint4*)(bPtr);
    bR[1] = *(const uint4*)(bPtr + (size_t)32 * K);

    float acc[4][4][4];
    #pragma unroll
    for (int mt = 0; mt < 4; mt++)
        #pragma unroll
        for (int nt = 0; nt < 4; nt++)
            #pragma unroll
            for (int r = 0; r < 4; r++) acc[mt][nt][r] = 0.f;

    const int a_row = (lgrp & 1) * 8 + lrow;
    const int a_col = (lgrp >> 1) * 8;
    const int b_row = (lgrp >> 1) * 8 + lrow;
    const int b_col = (lgrp & 1) * 8;

    for (int k0 = 0; k0 < K; k0 += BK) {
        #pragma unroll
        for (int i = 0; i < 4; i++)
            *(uint4*)&Ah[sr + 32 * i][sc] = aR[i];
        *(uint4*)&Bh[sr][sc]      = bR[0];
        *(uint4*)&Bh[sr + 32][sc] = bR[1];
        __syncthreads();

        if (k0 + BK < K) {
            #pragma unroll
            for (int i = 0; i < 4; i++)
                aR[i] = *(const uint4*)(aPtr + (size_t)(32 * i) * K + k0 + BK);
            bR[0] = *(const uint4*)(bPtr + k0 + BK);
            bR[1] = *(const uint4*)(bPtr + (size_t)32 * K + k0 + BK);
        }

        #pragma unroll
        for (int kk = 0; kk < 2; kk++) {
            const int kc = kk * 16;
            uint32_t afr[4][4], bfr[4][2];
            #pragma unroll
            for (int mt = 0; mt < 4; mt++) {
                uint32_t addr = smem_u32(&Ah[warpM * 64 + mt * 16 + a_row][kc + a_col]);
                LDMATRIX_X4(afr[mt][0], afr[mt][1], afr[mt][2], afr[mt][3], addr);
            }
            #pragma unroll
            for (int nb = 0; nb < 2; nb++) {
                uint32_t addr = smem_u32(&Bh[warpN * 32 + nb * 16 + b_row][kc + b_col]);
                LDMATRIX_X4(bfr[2 * nb][0], bfr[2 * nb][1],
                            bfr[2 * nb + 1][0], bfr[2 * nb + 1][1], addr);
            }
            #pragma unroll
            for (int mt = 0; mt < 4; mt++)
                #pragma unroll
                for (int nt = 0; nt < 4; nt++)
                    MMA_F16(acc[mt][nt], afr[mt][0], afr[mt][1], afr[mt][2], afr[mt][3],
                            bfr[nt][0], bfr[nt][1]);
        }
        __syncthreads();
    }

    #pragma unroll
    for (int mt = 0; mt < 4; mt++) {
        const int row = rowBase + warpM * 64 + mt * 16 + g;
        #pragma unroll
        for (int nt = 0; nt < 4; nt++) {
            const int col = colBase + warpN * 32 + nt * 8 + 2 * t;
            if (HALF_OUT) {
                __half2 lo = __floats2half2_rn(acc[mt][nt][0], acc[mt][nt][1]);
                __half2 hi = __floats2half2_rn(acc[mt][nt][2], acc[mt][nt][3]);
                *(__half2*)&Ch[(size_t)row * Nc + col]       = lo;
                *(__half2*)&Ch[(size_t)(row + 8) * Nc + col] = hi;
            } else {
                float b0 = 0.f, b1 = 0.f;
                if (BIAS) { b0 = bias[col]; b1 = bias[col + 1]; }
                float2 lo, hi;
                lo.x = acc[mt][nt][0] + b0; lo.y = acc[mt][nt][1] + b1;
                hi.x = acc[mt][nt][2] + b0; hi.y = acc[mt][nt][3] + b1;
                *(float2*)&C[(size_t)row * Nc + col]       = lo;
                *(float2*)&C[(size_t)(row + 8) * Nc + col] = hi;
            }
        }
    }
}

// =====================================================================
// K/V projection in ONE launch (fp32 FFMA; tiny: 462x640x768)
// =====================================================================
__global__ void __launch_bounds__(256) sgemm_kv(
    const float* __restrict__ A,
    const float* __restrict__ Wk,
    const float* __restrict__ Wv)
{
    constexpr int M = KVROWS, K = CD, NW = ID, NC = 2 * ID;
    __shared__ float As[16][64 + 4];
    __shared__ float Bs[16][64];

    const int tid = threadIdx.x;
    const int colBase = blockIdx.x * 64;
    const int rowBase = blockIdx.y * 64;
    const float* Bm = (colBase < NW) ? Wk : Wv;
    const int cb = (colBase < NW) ? colBase : colBase - NW;

    const int tx = tid & 15, ty = tid >> 4;
    const int ar = tid >> 2;
    const int ac = (tid & 3) << 2;
    const int br = tid >> 4;
    const int bc = (tid & 15) << 2;

    float acc[4][4];
    #pragma unroll
    for (int i = 0; i < 4; i++)
        #pragma unroll
        for (int j = 0; j < 4; j++) acc[i][j] = 0.f;

    for (int k0 = 0; k0 < K; k0 += 16) {
        const int grow = rowBase + ar;
        float4 a = (grow < M) ? *(const float4*)&A[(size_t)grow * K + k0 + ac]
                              : make_float4(0.f, 0.f, 0.f, 0.f);
        float4 b = *(const float4*)&Bm[(size_t)(k0 + br) * NW + cb + bc];
        As[ac+0][ar] = a.x; As[ac+1][ar] = a.y; As[ac+2][ar] = a.z; As[ac+3][ar] = a.w;
        *(float4*)&Bs[br][bc] = b;
        __syncthreads();

        #pragma unroll
        for (int kk = 0; kk < 16; kk++) {
            float av[4], bv[4];
            #pragma unroll
            for (int i = 0; i < 4; i++) av[i] = As[kk][ty * 4 + i];
            #pragma unroll
            for (int j = 0; j < 4; j++) bv[j] = Bs[kk][tx * 4 + j];
            #pragma unroll
            for (int i = 0; i < 4; i++)
                #pragma unroll
                for (int j = 0; j < 4; j++) acc[i][j] += av[i] * bv[j];
        }
        __syncthreads();
    }

    #pragma unroll
    for (int i = 0; i < 4; i++) {
        const int r = rowBase + ty * 4 + i;
        if (r < M) {
            float4 v; v.x = acc[i][0]; v.y = acc[i][1]; v.z = acc[i][2]; v.w = acc[i][3];
            *(float4*)&g_kv[(size_t)r * NC + colBase + tx * 4] = v;
        }
    }
}

// =====================================================================
// Attention v7: same as proven R14 structure, but q read as fp16
// (halves attn's dominant input stream). K/V stride 44, fp16 output.
// =====================================================================
constexpr int KVS = 44;
constexpr int ATTN_SMEM_B = (80 * KVS * 2) * 4;       // 28,160 B

__global__ void __launch_bounds__(256) attn_kernel(
    const __half* __restrict__ q,   // (B*N, 320) fp16
    float* __restrict__ sim)        // (B,H,N,77)
{
    float* Ks = (float*)smem_raw;              // [80][44]
    float* Vs = Ks + 80 * KVS;                 // [80][44]

    const int bh = blockIdx.y;
    const int b = bh >> 3;
    const int h = bh & 7;
    const int tid  = threadIdx.x;
    const int lane = tid & 31;
    const int wid  = tid >> 5;
    const int g = lane >> 2;
    const int t = lane & 3;
    const int nBase = blockIdx.x * 128;
    const int m0 = wid * 16;

    // ---- Q fragment loads from global fp16 (rows are warp-private) ----
    float qf[5][4];
    {
        const __half* qb = q + (size_t)(b * Nn + nBase + m0 + g) * ID + h * DH;
        #pragma unroll
        for (int ks = 0; ks < 5; ks++) {
            const int kc = ks * 8;
            qf[ks][0] = __half2float(qb[kc + t]);
            qf[ks][1] = __half2float(qb[8 * ID + kc + t]);
            qf[ks][2] = __half2float(qb[kc + t + 4]);
            qf[ks][3] = __half2float(qb[8 * ID + kc + t + 4]);
        }
    }

    // ---- stage K, V (tf32, rows 77..79 zeroed) ----
    for (int idx = tid; idx < CN * 10; idx += 256) {
        const int r = idx / 10, c4 = (idx - r * 10) * 4;
        const float* base = g_kv + (size_t)(b * CN + r) * (2 * ID) + h * DH + c4;
        *(uint4*)&Ks[r * KVS + c4] = tf32x4(*(const float4*)(base));
        *(uint4*)&Vs[r * KVS + c4] = tf32x4(*(const float4*)(base + ID));
    }
    if (tid < 120) {
        const int r = CN + tid / DH;
        const int c = tid % DH;
        Ks[r * KVS + c] = 0.f;
        Vs[r * KVS + c] = 0.f;
    }
    __syncthreads();

    // ---- QK^T: warp covers 16 rows x 80 cols ----
    float acc[10][4];
    #pragma unroll
    for (int nt = 0; nt < 10; nt++)
        #pragma unroll
        for (int r = 0; r < 4; r++) acc[nt][r] = 0.f;

    #pragma unroll
    for (int ks = 0; ks < 5; ks++) {
        const int kc = ks * 8;
        const uint32_t a0 = f2tf32(qf[ks][0]);
        const uint32_t a1 = f2tf32(qf[ks][1]);
        const uint32_t a2 = f2tf32(qf[ks][2]);
        const uint32_t a3 = f2tf32(qf[ks][3]);
        #pragma unroll
        for (int nt = 0; nt < 10; nt++) {
            const int n0 = nt * 8 + g;
            uint32_t b0 = __float_as_uint(Ks[n0 * KVS + kc + t    ]);
            uint32_t b1 = __float_as_uint(Ks[n0 * KVS + kc + t + 4]);
            MMA_TF32(acc[nt], a0, a1, a2, a3, b0, b1);
        }
    }
    #pragma unroll
    for (int nt = 0; nt < 10; nt++)
        #pragma unroll
        for (int r = 0; r < 4; r++) acc[nt][r] *= SCALE;

    // ---- sim write straight from registers (scalar stores: stride 77) ----
    {
        float* s0 = sim + ((size_t)bh * Nn + nBase + m0 + g) * CN;
        float* s1 = s0 + 8 * (size_t)CN;
        #pragma unroll
        for (int nt = 0; nt < 10; nt++) {
            const int c = nt * 8 + 2 * t;
            if (c < CN) {
                s0[c] = acc[nt][0];
                s1[c] = acc[nt][2];
            }
            if (c + 1 < CN) {
                s0[c + 1] = acc[nt][1];
                s1[c + 1] = acc[nt][3];
            }
        }
    }

    // ---- softmax in registers ----
    {
        const bool in0 = (t <= 2);
        const bool in1 = (t <= 1);
        float mx0 = -1e30f, mx1 = -1e30f;
        #pragma unroll
        for (int nt = 0; nt < 9; nt++) {
            mx0 = fmaxf(mx0, fmaxf(acc[nt][0], acc[nt][1]));
            mx1 = fmaxf(mx1, fmaxf(acc[nt][2], acc[nt][3]));
        }
        if (in0) { mx0 = fmaxf(mx0, acc[9][0]); mx1 = fmaxf(mx1, acc[9][2]); }
        if (in1) { mx0 = fmaxf(mx0, acc[9][1]); mx1 = fmaxf(mx1, acc[9][3]); }
        mx0 = fmaxf(mx0, __shfl_xor_sync(0xFFFFFFFF, mx0, 1));
        mx0 = fmaxf(mx0, __shfl_xor_sync(0xFFFFFFFF, mx0, 2));
        mx1 = fmaxf(mx1, __shfl_xor_sync(0xFFFFFFFF, mx1, 1));
        mx1 = fmaxf(mx1, __shfl_xor_sync(0xFFFFFFFF, mx1, 2));

        float s0 = 0.f, s1 = 0.f;
        #pragma unroll
        for (int nt = 0; nt < 10; nt++) {
            float e0 = fast_exp(acc[nt][0] - mx0);
            float e1 = fast_exp(acc[nt][1] - mx0);
            float e2 = fast_exp(acc[nt][2] - mx1);
            float e3 = fast_exp(acc[nt][3] - mx1);
            if (nt == 9) {
                if (!in0) { e0 = 0.f; e2 = 0.f; }
                if (!in1) { e1 = 0.f; e3 = 0.f; }
            }
            acc[nt][0] = e0; acc[nt][1] = e1;
            acc[nt][2] = e2; acc[nt][3] = e3;
            s0 += e0 + e1;
            s1 += e2 + e3;
        }
        s0 += __shfl_xor_sync(0xFFFFFFFF, s0, 1);
        s0 += __shfl_xor_sync(0xFFFFFFFF, s0, 2);
        s1 += __shfl_xor_sync(0xFFFFFFFF, s1, 1);
        s1 += __shfl_xor_sync(0xFFFFFFFF, s1, 2);
        const float inv0 = 1.f / s0;
        const float inv1 = 1.f / s1;

        float w = 1.f;
        if (b == 3) w = -2.f; else if (b == 5) w = 5.f;
        if (t == 1) { acc[0][0] *= w; acc[0][2] *= w; }

        #pragma unroll
        for (int nt = 0; nt < 10; nt++) {
            acc[nt][0] = __uint_as_float(f2tf32(acc[nt][0] * inv0));
            acc[nt][1] = __uint_as_float(f2tf32(acc[nt][1] * inv0));
            acc[nt][2] = __uint_as_float(f2tf32(acc[nt][2] * inv1));
            acc[nt][3] = __uint_as_float(f2tf32(acc[nt][3] * inv1));
        }
    }

    // ---- P V: A-fragments built by quad shuffles from acc ----
    {
        const int base = lane & ~3;
        const int srcA = base | (t >> 1);
        const int srcB = base | (2 + (t >> 1));
        const bool odd = (t & 1);

        float oacc[5][4];
        #pragma unroll
        for (int nt = 0; nt < 5; nt++)
            #pragma unroll
            for (int r = 0; r < 4; r++) oacc[nt][r] = 0.f;

        #pragma unroll
        for (int ks = 0; ks < 10; ks++) {
            const int kc = ks * 8;
            float xA0 = __shfl_sync(0xFFFFFFFF, acc[ks][0], srcA);
            float yA0 = __shfl_sync(0xFFFFFFFF, acc[ks][1], srcA);
            float xA1 = __shfl_sync(0xFFFFFFFF, acc[ks][2], srcA);
            float yA1 = __shfl_sync(0xFFFFFFFF, acc[ks][3], srcA);
            float xB0 = __shfl_sync(0xFFFFFFFF, acc[ks][0], srcB);
            float yB0 = __shfl_sync(0xFFFFFFFF, acc[ks][1], srcB);
            float xB1 = __shfl_sync(0xFFFFFFFF, acc[ks][2], srcB);
            float yB1 = __shfl_sync(0xFFFFFFFF, acc[ks][3], srcB);

            uint32_t a0 = __float_as_uint(odd ? yA0 : xA0);
            uint32_t a1 = __float_as_uint(odd ? yA1 : xA1);
            uint32_t a2 = __float_as_uint(odd ? yB0 : xB0);
            uint32_t a3 = __float_as_uint(odd ? yB1 : xB1);

            #pragma unroll
            for (int nt = 0; nt < 5; nt++) {
                const int n0 = nt * 8 + g;
                uint32_t b0 = __float_as_uint(Vs[(kc + t    ) * KVS + n0]);
                uint32_t b1 = __float_as_uint(Vs[(kc + t + 4) * KVS + n0]);
                MMA_TF32(oacc[nt], a0, a1, a2, a3, b0, b1);
            }
        }

        __half* o0 = g_oh + ((size_t)(b * Nn + nBase + m0 + g    )) * ID + h * DH;
        __half* o1 = g_oh + ((size_t)(b * Nn + nBase + m0 + g + 8)) * ID + h * DH;
        #pragma unroll
        for (int nt = 0; nt < 5; nt++) {
            const int c = nt * 8 + 2 * t;
            __half2 lo = __floats2half2_rn(oacc[nt][0], oacc[nt][1]);
            __half2 hi = __floats2half2_rn(oacc[nt][2], oacc[nt][3]);
            *(__half2*)(o0 + c) = lo;
            *(__half2*)(o1 + c) = hi;
        }
    }
}

// =====================================================================
// launch
// =====================================================================
extern "C" void kernel_launch(void* const* d_in, const int* in_sizes, int n_in,
                              void* d_out, int out_size)
{
    const float* x   = (const float*)d_in[0];
    const float* ctx = (const float*)d_in[1];
    const float* Wq  = (const float*)d_in[2];
    const float* Wk  = (const float*)d_in[3];
    const float* Wv  = (const float*)d_in[4];
    const float* Wo  = (const float*)d_in[5];
    const float* bo  = (const float*)d_in[6];
    // d_in[7] = time (unused: reweight always applies for time >= 0)

    float* out = (float*)d_out;                       // (B, N, 320)
    float* sim = out + (size_t)Bn * Nn * QD;          // (B, H, N, 77)

    __half *wt = nullptr, *xh = nullptr, *oh = nullptr, *qh = nullptr;
    cudaGetSymbolAddress((void**)&wt, g_wt);
    cudaGetSymbolAddress((void**)&xh, g_xh);
    cudaGetSymbolAddress((void**)&oh, g_oh);
    cudaGetSymbolAddress((void**)&qh, g_qh);

    cudaFuncSetAttribute(attn_kernel, cudaFuncAttributeMaxDynamicSharedMemorySize,
                         ATTN_SMEM_B);

    // x -> fp16 (7.86M elems, 4/thread)
    convert_x<<<(MROWS * ID) / (256 * 4), 256>>>(x);

    // transpose + fp16 convert Wq, Wo
    transpose_w<<<dim3(10, 10, 2), dim3(32, 8)>>>(Wq, Wo);

    // K & V projections (one launch)
    sgemm_kv<<<dim3((2 * ID) / 64, (KVROWS + 63) / 64), 256>>>(ctx, Wk, Wv);

    // Q projection -> fp16 g_qh (R14 gemm, HALF_OUT)
    gemm_h16<false, true><<<dim3(320 / 64, MROWS / 128), 128>>>(
        xh, wt, nullptr, nullptr, qh);

    // fused attention (fp16 q input, fp16 o output)
    attn_kernel<<<dim3(Nn / 128, Bn * Hh), 256, ATTN_SMEM_B>>>(qh, sim);

    // output projection + bias -> fp32 out
    gemm_h16<true, false><<<dim3(320 / 64, MROWS / 128), 128>>>(
        oh, wt + 320 * 320, bo, out, nullptr);
}

// round 17
// speedup vs baseline: 1.1561x; 1.1261x over previous
#include <cuda_runtime.h>
#include <cuda_fp16.h>
#include <cstdint>
#include <cstddef>

// ---------------- problem constants ----------------
constexpr int Bn  = 6;
constexpr int Nn  = 4096;
constexpr int QD  = 320;
constexpr int CN  = 77;
constexpr int CD  = 768;
constexpr int Hh  = 8;
constexpr int DH  = 40;
constexpr int ID  = Hh * DH;          // 320 inner dim
constexpr float SCALE = 0.15811388300841897f; // 40^-0.5

constexpr int MROWS = Bn * Nn;        // 24576
constexpr int KVROWS = Bn * CN;       // 462
constexpr size_t KVOFF = (size_t)KVROWS * 2 * ID;   // one split-K half

// single extern shared symbol (attn only)
extern __shared__ char smem_raw[];

// ---------------- scratch (static device memory; no allocs allowed) ------
__device__ __half g_qh[ (size_t)MROWS * ID ];     // q projection, fp16
__device__ __half g_oh[ (size_t)MROWS * ID ];     // attn@v merged heads, fp16
__device__ __half g_xh[ (size_t)MROWS * ID ];     // x converted to fp16
__device__ float  g_kv2[ 2 * KVOFF ];             // split-K halves of K|V proj
__device__ __half g_wt[ 2 * 320 * 320 ];          // Wq^T, Wo^T (fp16, N-major)

// ---------------- helpers ----------------
__device__ __forceinline__ uint32_t smem_u32(const void* p) {
    uint32_t a;
    asm("{ .reg .u64 t; cvta.to.shared.u64 t, %1; cvt.u32.u64 %0, t; }" : "=r"(a) : "l"(p));
    return a;
}
__device__ __forceinline__ uint32_t f2tf32(float f) {
    uint32_t r;
    asm("cvt.rna.tf32.f32 %0, %1;" : "=r"(r) : "f"(f));
    return r;
}
// FFMA-only exp (relative error ~2.5e-6)
__device__ __forceinline__ float fast_exp(float x) {
    x = fmaxf(x, -60.f);
    float y = x * 1.4426950408889634f;
    int   n = __float2int_rn(y);
    float f = y - (float)n;
    float t = f * 0.6931471805599453f;
    float p = 8.3333333333e-3f;
    p = fmaf(p, t, 4.1666666667e-2f);
    p = fmaf(p, t, 1.6666666667e-1f);
    p = fmaf(p, t, 0.5f);
    p = fmaf(p, t, 1.0f);
    p = fmaf(p, t, 1.0f);
    return __int_as_float(__float_as_int(p) + (n << 23));
}

#define MMA_TF32(acc, a0, a1, a2, a3, b0, b1)                                   \
    asm volatile(                                                               \
        "mma.sync.aligned.m16n8k8.row.col.f32.tf32.tf32.f32 "                   \
        "{%0,%1,%2,%3}, {%4,%5,%6,%7}, {%8,%9}, {%0,%1,%2,%3};\n"               \
        : "+f"(acc[0]), "+f"(acc[1]), "+f"(acc[2]), "+f"(acc[3])                \
        : "r"(a0), "r"(a1), "r"(a2), "r"(a3), "r"(b0), "r"(b1))

#define MMA_F16(acc, a0, a1, a2, a3, b0, b1)                                    \
    asm volatile(                                                               \
        "mma.sync.aligned.m16n8k16.row.col.f32.f16.f16.f32 "                    \
        "{%0,%1,%2,%3}, {%4,%5,%6,%7}, {%8,%9}, {%0,%1,%2,%3};\n"               \
        : "+f"(acc[0]), "+f"(acc[1]), "+f"(acc[2]), "+f"(acc[3])                \
        : "r"(a0), "r"(a1), "r"(a2), "r"(a3), "r"(b0), "r"(b1))

#define LDMATRIX_X4(r0, r1, r2, r3, addr)                                       \
    asm volatile("ldmatrix.sync.aligned.m8n8.x4.shared.b16 {%0,%1,%2,%3}, [%4];"\
        : "=r"(r0), "=r"(r1), "=r"(r2), "=r"(r3) : "r"(addr))

// =====================================================================
// prep: fused x->fp16 convert (blocks [0, NXB)) and W transpose+fp16
// (blocks [NXB, NXB+200)). 256 threads each.
// =====================================================================
constexpr int NXB = (MROWS * ID) / (256 * 4);   // 7680

__global__ void __launch_bounds__(256) prep(
    const float* __restrict__ x,
    const float* __restrict__ Wq,
    const float* __restrict__ Wo)
{
    if (blockIdx.x < NXB) {
        const size_t i = ((size_t)blockIdx.x * 256 + threadIdx.x) * 4;
        float4 v = *(const float4*)(x + i);
        __half2 h0 = __floats2half2_rn(v.x, v.y);
        __half2 h1 = __floats2half2_rn(v.z, v.w);
        uint2 u;
        u.x = *(const uint32_t*)&h0;
        u.y = *(const uint32_t*)&h1;
        *(uint2*)(g_xh + i) = u;
    } else {
        __shared__ float tile[32][33];
        const int bi  = blockIdx.x - NXB;       // 0..199
        const int sel = bi / 100;
        const int rem = bi - sel * 100;
        const int by  = rem / 10;               // k block
        const int bx  = rem - by * 10;          // n block
        const float* W = (sel == 0) ? Wq : Wo;
        __half* Wt = g_wt + (size_t)sel * 320 * 320;
        const int kBase = by * 32;
        const int nBase = bx * 32;
        const int tx = threadIdx.x & 31;
        const int ty = threadIdx.x >> 5;        // 0..7
        #pragma unroll
        for (int i = 0; i < 4; i++)
            tile[ty + 8 * i][tx] = W[(size_t)(kBase + ty + 8 * i) * 320 + nBase + tx];
        __syncthreads();
        #pragma unroll
        for (int i = 0; i < 4; i++)
            Wt[(size_t)(nBase + ty + 8 * i) * 320 + kBase + tx] =
                __float2half_rn(tile[tx][ty + 8 * i]);
    }
}

// =====================================================================
// FP16 tensor-core GEMM (R14-proven): BM=128, BN=64, BK=32, 128 threads
// (4 warps 2Mx2N, warp 64x32), ldmatrix.x4, stride-40 smem.
// =====================================================================
template<bool BIAS, bool HALF_OUT>
__global__ void __launch_bounds__(128) gemm_h16(
    const __half* __restrict__ A,      // (24576, 320) fp16
    const __half* __restrict__ Wt,     // (320, 320) N-major fp16
    const float*  __restrict__ bias,   // (320) or null
    float* __restrict__ C,             // fp32 out (when !HALF_OUT)
    __half* __restrict__ Ch)           // fp16 out (when HALF_OUT)
{
    constexpr int Nc = 320, K = 320;
    constexpr int BK = 32;
    constexpr int HS = 40;

    __shared__ __half Ah[128][HS];
    __shared__ __half Bh[64][HS];

    const int tid  = threadIdx.x;
    const int lane = tid & 31;
    const int wid  = tid >> 5;
    const int warpM = wid & 1;
    const int warpN = wid >> 1;
    const int g = lane >> 2;
    const int t = lane & 3;
    const int lrow = lane & 7;
    const int lgrp = lane >> 3;

    const int rowBase = blockIdx.y * 128;
    const int colBase = blockIdx.x * 64;

    const int sr = tid >> 2;          // 0..31
    const int sc = (tid & 3) * 8;     // half col {0,8,16,24}

    const __half* aPtr = A  + (size_t)(rowBase + sr) * K + sc;
    const __half* bPtr = Wt + (size_t)(colBase + sr) * K + sc;

    uint4 aR[4], bR[2];
    #pragma unroll
    for (int i = 0; i < 4; i++) aR[i] = *(const uint4*)(aPtr + (size_t)(32 * i) * K);
    bR[0] = *(const uint4*)(bPtr);
    bR[1] = *(const uint4*)(bPtr + (size_t)32 * K);

    float acc[4][4][4];
    #pragma unroll
    for (int mt = 0; mt < 4; mt++)
        #pragma unroll
        for (int nt = 0; nt < 4; nt++)
            #pragma unroll
            for (int r = 0; r < 4; r++) acc[mt][nt][r] = 0.f;

    const int a_row = (lgrp & 1) * 8 + lrow;
    const int a_col = (lgrp >> 1) * 8;
    const int b_row = (lgrp >> 1) * 8 + lrow;
    const int b_col = (lgrp & 1) * 8;

    for (int k0 = 0; k0 < K; k0 += BK) {
        #pragma unroll
        for (int i = 0; i < 4; i++)
            *(uint4*)&Ah[sr + 32 * i][sc] = aR[i];
        *(uint4*)&Bh[sr][sc]      = bR[0];
        *(uint4*)&Bh[sr + 32][sc] = bR[1];
        __syncthreads();

        if (k0 + BK < K) {
            #pragma unroll
            for (int i = 0; i < 4; i++)
                aR[i] = *(const uint4*)(aPtr + (size_t)(32 * i) * K + k0 + BK);
            bR[0] = *(const uint4*)(bPtr + k0 + BK);
            bR[1] = *(const uint4*)(bPtr + (size_t)32 * K + k0 + BK);
        }

        #pragma unroll
        for (int kk = 0; kk < 2; kk++) {
            const int kc = kk * 16;
            uint32_t afr[4][4], bfr[4][2];
            #pragma unroll
            for (int mt = 0; mt < 4; mt++) {
                uint32_t addr = smem_u32(&Ah[warpM * 64 + mt * 16 + a_row][kc + a_col]);
                LDMATRIX_X4(afr[mt][0], afr[mt][1], afr[mt][2], afr[mt][3], addr);
            }
            #pragma unroll
            for (int nb = 0; nb < 2; nb++) {
                uint32_t addr = smem_u32(&Bh[warpN * 32 + nb * 16 + b_row][kc + b_col]);
                LDMATRIX_X4(bfr[2 * nb][0], bfr[2 * nb][1],
                            bfr[2 * nb + 1][0], bfr[2 * nb + 1][1], addr);
            }
            #pragma unroll
            for (int mt = 0; mt < 4; mt++)
                #pragma unroll
                for (int nt = 0; nt < 4; nt++)
                    MMA_F16(acc[mt][nt], afr[mt][0], afr[mt][1], afr[mt][2], afr[mt][3],
                            bfr[nt][0], bfr[nt][1]);
        }
        __syncthreads();
    }

    #pragma unroll
    for (int mt = 0; mt < 4; mt++) {
        const int row = rowBase + warpM * 64 + mt * 16 + g;
        #pragma unroll
        for (int nt = 0; nt < 4; nt++) {
            const int col = colBase + warpN * 32 + nt * 8 + 2 * t;
            if (HALF_OUT) {
                __half2 lo = __floats2half2_rn(acc[mt][nt][0], acc[mt][nt][1]);
                __half2 hi = __floats2half2_rn(acc[mt][nt][2], acc[mt][nt][3]);
                *(__half2*)&Ch[(size_t)row * Nc + col]       = lo;
                *(__half2*)&Ch[(size_t)(row + 8) * Nc + col] = hi;
            } else {
                float b0 = 0.f, b1 = 0.f;
                if (BIAS) { b0 = bias[col]; b1 = bias[col + 1]; }
                float2 lo, hi;
                lo.x = acc[mt][nt][0] + b0; lo.y = acc[mt][nt][1] + b1;
                hi.x = acc[mt][nt][2] + b0; hi.y = acc[mt][nt][3] + b1;
                *(float2*)&C[(size_t)row * Nc + col]       = lo;
                *(float2*)&C[(size_t)(row + 8) * Nc + col] = hi;
            }
        }
    }
}

// =====================================================================
// K/V projection, split-K=2: blockIdx.z selects K half [z*384,(z+1)*384).
// Each half written to g_kv2 + z*KVOFF; attention staging sums them.
// =====================================================================
__global__ void __launch_bounds__(256) sgemm_kv(
    const float* __restrict__ A,
    const float* __restrict__ Wk,
    const float* __restrict__ Wv)
{
    constexpr int M = KVROWS, NW = ID, NC = 2 * ID;
    constexpr int KH = CD / 2;          // 384 per split
    __shared__ float As[16][64 + 4];
    __shared__ float Bs[16][64];

    const int tid = threadIdx.x;
    const int colBase = blockIdx.x * 64;
    const int rowBase = blockIdx.y * 64;
    const int kOff = blockIdx.z * KH;
    float* dst = g_kv2 + (size_t)blockIdx.z * KVOFF;

    const float* Bm = (colBase < NW) ? Wk : Wv;
    const int cb = (colBase < NW) ? colBase : colBase - NW;

    const int tx = tid & 15, ty = tid >> 4;
    const int ar = tid >> 2;
    const int ac = (tid & 3) << 2;
    const int br = tid >> 4;
    const int bc = (tid & 15) << 2;

    float acc[4][4];
    #pragma unroll
    for (int i = 0; i < 4; i++)
        #pragma unroll
        for (int j = 0; j < 4; j++) acc[i][j] = 0.f;

    for (int k0 = kOff; k0 < kOff + KH; k0 += 16) {
        const int grow = rowBase + ar;
        float4 a = (grow < M) ? *(const float4*)&A[(size_t)grow * CD + k0 + ac]
                              : make_float4(0.f, 0.f, 0.f, 0.f);
        float4 b = *(const float4*)&Bm[(size_t)(k0 + br) * NW + cb + bc];
        As[ac+0][ar] = a.x; As[ac+1][ar] = a.y; As[ac+2][ar] = a.z; As[ac+3][ar] = a.w;
        *(float4*)&Bs[br][bc] = b;
        __syncthreads();

        #pragma unroll
        for (int kk = 0; kk < 16; kk++) {
            float av[4], bv[4];
            #pragma unroll
            for (int i = 0; i < 4; i++) av[i] = As[kk][ty * 4 + i];
            #pragma unroll
            for (int j = 0; j < 4; j++) bv[j] = Bs[kk][tx * 4 + j];
            #pragma unroll
            for (int i = 0; i < 4; i++)
                #pragma unroll
                for (int j = 0; j < 4; j++) acc[i][j] += av[i] * bv[j];
        }
        __syncthreads();
    }

    #pragma unroll
    for (int i = 0; i < 4; i++) {
        const int r = rowBase + ty * 4 + i;
        if (r < M) {
            float4 v; v.x = acc[i][0]; v.y = acc[i][1]; v.z = acc[i][2]; v.w = acc[i][3];
            *(float4*)&dst[(size_t)r * NC + colBase + tx * 4] = v;
        }
    }
}

// =====================================================================
// Attention v7.1: as R16, staging sums the two split-K halves of K/V.
// =====================================================================
constexpr int KVS = 44;
constexpr int ATTN_SMEM_B = (80 * KVS * 2) * 4;       // 28,160 B

__global__ void __launch_bounds__(256) attn_kernel(
    const __half* __restrict__ q,   // (B*N, 320) fp16
    float* __restrict__ sim)        // (B,H,N,77)
{
    float* Ks = (float*)smem_raw;              // [80][44]
    float* Vs = Ks + 80 * KVS;                 // [80][44]

    const int bh = blockIdx.y;
    const int b = bh >> 3;
    const int h = bh & 7;
    const int tid  = threadIdx.x;
    const int lane = tid & 31;
    const int wid  = tid >> 5;
    const int g = lane >> 2;
    const int t = lane & 3;
    const int nBase = blockIdx.x * 128;
    const int m0 = wid * 16;

    // ---- Q fragment loads from global fp16 ----
    float qf[5][4];
    {
        const __half* qb = q + (size_t)(b * Nn + nBase + m0 + g) * ID + h * DH;
        #pragma unroll
        for (int ks = 0; ks < 5; ks++) {
            const int kc = ks * 8;
            qf[ks][0] = __half2float(qb[kc + t]);
            qf[ks][1] = __half2float(qb[8 * ID + kc + t]);
            qf[ks][2] = __half2float(qb[kc + t + 4]);
            qf[ks][3] = __half2float(qb[8 * ID + kc + t + 4]);
        }
    }

    // ---- stage K, V: sum split-K halves, tf32-round; rows 77..79 zero ----
    for (int idx = tid; idx < CN * 10; idx += 256) {
        const int r = idx / 10, c4 = (idx - r * 10) * 4;
        const size_t off = (size_t)(b * CN + r) * (2 * ID) + h * DH + c4;
        float4 k0 = *(const float4*)(g_kv2 + off);
        float4 k1 = *(const float4*)(g_kv2 + KVOFF + off);
        float4 v0 = *(const float4*)(g_kv2 + off + ID);
        float4 v1 = *(const float4*)(g_kv2 + KVOFF + off + ID);
        uint4 ku, vu;
        ku.x = f2tf32(k0.x + k1.x); ku.y = f2tf32(k0.y + k1.y);
        ku.z = f2tf32(k0.z + k1.z); ku.w = f2tf32(k0.w + k1.w);
        vu.x = f2tf32(v0.x + v1.x); vu.y = f2tf32(v0.y + v1.y);
        vu.z = f2tf32(v0.z + v1.z); vu.w = f2tf32(v0.w + v1.w);
        *(uint4*)&Ks[r * KVS + c4] = ku;
        *(uint4*)&Vs[r * KVS + c4] = vu;
    }
    if (tid < 120) {
        const int r = CN + tid / DH;
        const int c = tid % DH;
        Ks[r * KVS + c] = 0.f;
        Vs[r * KVS + c] = 0.f;
    }
    __syncthreads();

    // ---- QK^T ----
    float acc[10][4];
    #pragma unroll
    for (int nt = 0; nt < 10; nt++)
        #pragma unroll
        for (int r = 0; r < 4; r++) acc[nt][r] = 0.f;

    #pragma unroll
    for (int ks = 0; ks < 5; ks++) {
        const int kc = ks * 8;
        const uint32_t a0 = f2tf32(qf[ks][0]);
        const uint32_t a1 = f2tf32(qf[ks][1]);
        const uint32_t a2 = f2tf32(qf[ks][2]);
        const uint32_t a3 = f2tf32(qf[ks][3]);
        #pragma unroll
        for (int nt = 0; nt < 10; nt++) {
            const int n0 = nt * 8 + g;
            uint32_t b0 = __float_as_uint(Ks[n0 * KVS + kc + t    ]);
            uint32_t b1 = __float_as_uint(Ks[n0 * KVS + kc + t + 4]);
            MMA_TF32(acc[nt], a0, a1, a2, a3, b0, b1);
        }
    }
    #pragma unroll
    for (int nt = 0; nt < 10; nt++)
        #pragma unroll
        for (int r = 0; r < 4; r++) acc[nt][r] *= SCALE;

    // ---- sim write ----
    {
        float* s0 = sim + ((size_t)bh * Nn + nBase + m0 + g) * CN;
        float* s1 = s0 + 8 * (size_t)CN;
        #pragma unroll
        for (int nt = 0; nt < 10; nt++) {
            const int c = nt * 8 + 2 * t;
            if (c < CN) {
                s0[c] = acc[nt][0];
                s1[c] = acc[nt][2];
            }
            if (c + 1 < CN) {
                s0[c + 1] = acc[nt][1];
                s1[c + 1] = acc[nt][3];
            }
        }
    }

    // ---- softmax in registers ----
    {
        const bool in0 = (t <= 2);
        const bool in1 = (t <= 1);
        float mx0 = -1e30f, mx1 = -1e30f;
        #pragma unroll
        for (int nt = 0; nt < 9; nt++) {
            mx0 = fmaxf(mx0, fmaxf(acc[nt][0], acc[nt][1]));
            mx1 = fmaxf(mx1, fmaxf(acc[nt][2], acc[nt][3]));
        }
        if (in0) { mx0 = fmaxf(mx0, acc[9][0]); mx1 = fmaxf(mx1, acc[9][2]); }
        if (in1) { mx0 = fmaxf(mx0, acc[9][1]); mx1 = fmaxf(mx1, acc[9][3]); }
        mx0 = fmaxf(mx0, __shfl_xor_sync(0xFFFFFFFF, mx0, 1));
        mx0 = fmaxf(mx0, __shfl_xor_sync(0xFFFFFFFF, mx0, 2));
        mx1 = fmaxf(mx1, __shfl_xor_sync(0xFFFFFFFF, mx1, 1));
        mx1 = fmaxf(mx1, __shfl_xor_sync(0xFFFFFFFF, mx1, 2));

        float s0 = 0.f, s1 = 0.f;
        #pragma unroll
        for (int nt = 0; nt < 10; nt++) {
            float e0 = fast_exp(acc[nt][0] - mx0);
            float e1 = fast_exp(acc[nt][1] - mx0);
            float e2 = fast_exp(acc[nt][2] - mx1);
            float e3 = fast_exp(acc[nt][3] - mx1);
            if (nt == 9) {
                if (!in0) { e0 = 0.f; e2 = 0.f; }
                if (!in1) { e1 = 0.f; e3 = 0.f; }
            }
            acc[nt][0] = e0; acc[nt][1] = e1;
            acc[nt][2] = e2; acc[nt][3] = e3;
            s0 += e0 + e1;
            s1 += e2 + e3;
        }
        s0 += __shfl_xor_sync(0xFFFFFFFF, s0, 1);
        s0 += __shfl_xor_sync(0xFFFFFFFF, s0, 2);
        s1 += __shfl_xor_sync(0xFFFFFFFF, s1, 1);
        s1 += __shfl_xor_sync(0xFFFFFFFF, s1, 2);
        const float inv0 = 1.f / s0;
        const float inv1 = 1.f / s1;

        float w = 1.f;
        if (b == 3) w = -2.f; else if (b == 5) w = 5.f;
        if (t == 1) { acc[0][0] *= w; acc[0][2] *= w; }

        #pragma unroll
        for (int nt = 0; nt < 10; nt++) {
            acc[nt][0] = __uint_as_float(f2tf32(acc[nt][0] * inv0));
            acc[nt][1] = __uint_as_float(f2tf32(acc[nt][1] * inv0));
            acc[nt][2] = __uint_as_float(f2tf32(acc[nt][2] * inv1));
            acc[nt][3] = __uint_as_float(f2tf32(acc[nt][3] * inv1));
        }
    }

    // ---- P V via quad-shuffle fragments ----
    {
        const int base = lane & ~3;
        const int srcA = base | (t >> 1);
        const int srcB = base | (2 + (t >> 1));
        const bool odd = (t & 1);

        float oacc[5][4];
        #pragma unroll
        for (int nt = 0; nt < 5; nt++)
            #pragma unroll
            for (int r = 0; r < 4; r++) oacc[nt][r] = 0.f;

        #pragma unroll
        for (int ks = 0; ks < 10; ks++) {
            const int kc = ks * 8;
            float xA0 = __shfl_sync(0xFFFFFFFF, acc[ks][0], srcA);
            float yA0 = __shfl_sync(0xFFFFFFFF, acc[ks][1], srcA);
            float xA1 = __shfl_sync(0xFFFFFFFF, acc[ks][2], srcA);
            float yA1 = __shfl_sync(0xFFFFFFFF, acc[ks][3], srcA);
            float xB0 = __shfl_sync(0xFFFFFFFF, acc[ks][0], srcB);
            float yB0 = __shfl_sync(0xFFFFFFFF, acc[ks][1], srcB);
            float xB1 = __shfl_sync(0xFFFFFFFF, acc[ks][2], srcB);
            float yB1 = __shfl_sync(0xFFFFFFFF, acc[ks][3], srcB);

            uint32_t a0 = __float_as_uint(odd ? yA0 : xA0);
            uint32_t a1 = __float_as_uint(odd ? yA1 : xA1);
            uint32_t a2 = __float_as_uint(odd ? yB0 : xB0);
            uint32_t a3 = __float_as_uint(odd ? yB1 : xB1);

            #pragma unroll
            for (int nt = 0; nt < 5; nt++) {
                const int n0 = nt * 8 + g;
                uint32_t b0 = __float_as_uint(Vs[(kc + t    ) * KVS + n0]);
                uint32_t b1 = __float_as_uint(Vs[(kc + t + 4) * KVS + n0]);
                MMA_TF32(oacc[nt], a0, a1, a2, a3, b0, b1);
            }
        }

        __half* o0 = g_oh + ((size_t)(b * Nn + nBase + m0 + g    )) * ID + h * DH;
        __half* o1 = g_oh + ((size_t)(b * Nn + nBase + m0 + g + 8)) * ID + h * DH;
        #pragma unroll
        for (int nt = 0; nt < 5; nt++) {
            const int c = nt * 8 + 2 * t;
            __half2 lo = __floats2half2_rn(oacc[nt][0], oacc[nt][1]);
            __half2 hi = __floats2half2_rn(oacc[nt][2], oacc[nt][3]);
            *(__half2*)(o0 + c) = lo;
            *(__half2*)(o1 + c) = hi;
        }
    }
}

// =====================================================================
// launch
// =====================================================================
extern "C" void kernel_launch(void* const* d_in, const int* in_sizes, int n_in,
                              void* d_out, int out_size)
{
    const float* x   = (const float*)d_in[0];
    const float* ctx = (const float*)d_in[1];
    const float* Wq  = (const float*)d_in[2];
    const float* Wk  = (const float*)d_in[3];
    const float* Wv  = (const float*)d_in[4];
    const float* Wo  = (const float*)d_in[5];
    const float* bo  = (const float*)d_in[6];
    // d_in[7] = time (unused: reweight always applies for time >= 0)

    float* out = (float*)d_out;                       // (B, N, 320)
    float* sim = out + (size_t)Bn * Nn * QD;          // (B, H, N, 77)

    __half *wt = nullptr, *xh = nullptr, *oh = nullptr, *qh = nullptr;
    cudaGetSymbolAddress((void**)&wt, g_wt);
    cudaGetSymbolAddress((void**)&xh, g_xh);
    cudaGetSymbolAddress((void**)&oh, g_oh);
    cudaGetSymbolAddress((void**)&qh, g_qh);

    cudaFuncSetAttribute(attn_kernel, cudaFuncAttributeMaxDynamicSharedMemorySize,
                         ATTN_SMEM_B);

    // fused prep: x->fp16 + W transpose/convert
    prep<<<NXB + 200, 256>>>(x, Wq, Wo);

    // K & V projections, split-K=2
    sgemm_kv<<<dim3((2 * ID) / 64, (KVROWS + 63) / 64, 2), 256>>>(ctx, Wk, Wv);

    // Q projection -> fp16 g_qh
    gemm_h16<false, true><<<dim3(320 / 64, MROWS / 128), 128>>>(
        xh, wt, nullptr, nullptr, qh);

    // fused attention (sums split-K halves while staging)
    attn_kernel<<<dim3(Nn / 128, Bn * Hh), 256, ATTN_SMEM_B>>>(qh, sim);

    // output projection + bias -> fp32 out
    gemm_h16<true, false><<<dim3(320 / 64, MROWS / 128), 128>>>(
        oh, wt + 320 * 320, bo, out, nullptr);
}